// round 2
// baseline (speedup 1.0000x reference)
#include <cuda_runtime.h>

// CFGGraphEncoder: 3-layer GCN, N=100000 nodes (11 feats), E=1600000 edges.
// layer(x,W,b) = tanh( (A@x + 2x)@W + b ) = tanh( A@(xW) + 2(xW) + b )
// => per layer: z = x@W ; agg = segsum(z over edges) ; x' = tanh(agg + 2z + b)
// Output: [N,96] concat(x1,x2,x3) followed by 64 graph sizes (bincount).
//
// NOTE: harness delivers integer inputs as int32 (int64 narrowed), so
// edge_index / batch_indices are read as const int*.

#define MAXN 100000
#define MAXE 1600000

// Scratch (allocation-free contract: __device__ globals)
__device__ int2 g_edge[MAXE];                       // packed (row, col) int32
__device__ __align__(16) float g_z[MAXN * 32];      // z = x @ W
__device__ __align__(16) float g_agg[MAXN * 32];    // segment sums

// ---------------------------------------------------------------------------
// Pack edge_index [2,E] (int32) -> int2 once per launch.
// ---------------------------------------------------------------------------
__global__ void prep_edges_kernel(const int* __restrict__ ei, int E) {
    int t = blockIdx.x * blockDim.x + threadIdx.x;
    if (t < E) {
        int2 rc;
        rc.x = ei[t];        // row (scatter target)
        rc.y = ei[E + t];    // col (gather source)
        g_edge[t] = rc;
    }
}

// ---------------------------------------------------------------------------
// graph_sizes: batch_indices is SORTED -> binary search per graph id. 64 thr.
// ---------------------------------------------------------------------------
__device__ __forceinline__ int lower_bound_i(const int* __restrict__ b,
                                             int n, int v) {
    int lo = 0, hi = n;
    while (lo < hi) {
        int mid = (lo + hi) >> 1;
        if (b[mid] < v) lo = mid + 1; else hi = mid;
    }
    return lo;
}

__global__ void graph_sizes_kernel(const int* __restrict__ batch, int N,
                                   float* __restrict__ out_sizes) {
    int g = threadIdx.x;  // 0..63
    int c = lower_bound_i(batch, N, g + 1) - lower_bound_i(batch, N, g);
    out_sizes[g] = (float)c;
}

// ---------------------------------------------------------------------------
// init: z = x0 @ W1 (x0 is [N,11]); zero agg. One thread per node.
// ---------------------------------------------------------------------------
__global__ void init_kernel(const float* __restrict__ x0,
                            const float* __restrict__ W1, int N) {
    __shared__ float sW[11 * 32];
    for (int i = threadIdx.x; i < 11 * 32; i += blockDim.x) sW[i] = W1[i];
    __syncthreads();
    int i = blockIdx.x * blockDim.x + threadIdx.x;
    if (i >= N) return;

    float x[11];
#pragma unroll
    for (int k = 0; k < 11; k++) x[k] = x0[i * 11 + k];

    float4* zp = (float4*)(g_z + (size_t)i * 32);
    float4* ap = (float4*)(g_agg + (size_t)i * 32);
#pragma unroll
    for (int q = 0; q < 8; q++) {
        float4 acc = make_float4(0.f, 0.f, 0.f, 0.f);
#pragma unroll
        for (int k = 0; k < 11; k++) {
            float xv = x[k];
            const float* w = &sW[k * 32 + q * 4];
            acc.x += xv * w[0];
            acc.y += xv * w[1];
            acc.z += xv * w[2];
            acc.w += xv * w[3];
        }
        zp[q] = acc;
        ap[q] = make_float4(0.f, 0.f, 0.f, 0.f);
    }
}

// ---------------------------------------------------------------------------
// scatter: agg[row] += z[col]. t = (edge<<3)|quad; each thread moves float4.
// red.global.add.v4.f32: 16B vector reduction, no return (REDG path).
// ---------------------------------------------------------------------------
__global__ void scatter_kernel(int E8) {
    int t = blockIdx.x * blockDim.x + threadIdx.x;
    if (t >= E8) return;
    int e = t >> 3;
    int q = t & 7;
    int2 rc = g_edge[e];
    const float4* zp = (const float4*)g_z;
    float4 v = __ldg(&zp[(size_t)rc.y * 8 + q]);
    float* a = g_agg + (size_t)rc.x * 32 + q * 4;
    asm volatile("red.global.add.v4.f32 [%0], {%1,%2,%3,%4};"
                 :: "l"(a), "f"(v.x), "f"(v.y), "f"(v.z), "f"(v.w)
                 : "memory");
}

// ---------------------------------------------------------------------------
// node epilogue + next-layer GEMM fused:
//   h = tanh(agg + 2z + b)          -> out[:, 32*layer : 32*layer+32]
//   if HAS_NEXT: z = h @ Wn ; agg = 0
// One thread per node.
// ---------------------------------------------------------------------------
template <bool HAS_NEXT>
__global__ void node_kernel(const float* __restrict__ bvec,
                            const float* __restrict__ Wn,
                            float* __restrict__ out, int N, int layer) {
    __shared__ float sW[32 * 32];
    __shared__ float sb[32];
    if (threadIdx.x < 32) sb[threadIdx.x] = bvec[threadIdx.x];
    if (HAS_NEXT) {
        for (int i = threadIdx.x; i < 1024; i += blockDim.x) sW[i] = Wn[i];
    }
    __syncthreads();

    int i = blockIdx.x * blockDim.x + threadIdx.x;
    if (i >= N) return;

    float4* zp = (float4*)(g_z + (size_t)i * 32);
    float4* ap = (float4*)(g_agg + (size_t)i * 32);

    float h[32];
#pragma unroll
    for (int q = 0; q < 8; q++) {
        float4 a = ap[q];
        float4 z = zp[q];
        h[q * 4 + 0] = tanhf(a.x + 2.f * z.x + sb[q * 4 + 0]);
        h[q * 4 + 1] = tanhf(a.y + 2.f * z.y + sb[q * 4 + 1]);
        h[q * 4 + 2] = tanhf(a.z + 2.f * z.z + sb[q * 4 + 2]);
        h[q * 4 + 3] = tanhf(a.w + 2.f * z.w + sb[q * 4 + 3]);
    }

    // out[i*96 + 32*layer + j]; byte offset 384i+128l is 16B aligned.
    float4* op = (float4*)(out + (size_t)i * 96 + 32 * layer);
#pragma unroll
    for (int q = 0; q < 8; q++) {
        op[q] = make_float4(h[q * 4 + 0], h[q * 4 + 1], h[q * 4 + 2], h[q * 4 + 3]);
    }

    if (HAS_NEXT) {
#pragma unroll
        for (int q = 0; q < 8; q++) {
            float4 acc = make_float4(0.f, 0.f, 0.f, 0.f);
#pragma unroll
            for (int k = 0; k < 32; k++) {
                float hv = h[k];
                const float* w = &sW[k * 32 + q * 4];
                acc.x += hv * w[0];
                acc.y += hv * w[1];
                acc.z += hv * w[2];
                acc.w += hv * w[3];
            }
            zp[q] = acc;
            ap[q] = make_float4(0.f, 0.f, 0.f, 0.f);
        }
    }
}

// ---------------------------------------------------------------------------
// Launch
// ---------------------------------------------------------------------------
extern "C" void kernel_launch(void* const* d_in, const int* in_sizes, int n_in,
                              void* d_out, int out_size) {
    const float* x0    = (const float*)d_in[0];
    const int*   ei    = (const int*)d_in[1];
    const int*   batch = (const int*)d_in[2];
    const float* W1    = (const float*)d_in[3];
    const float* b1    = (const float*)d_in[4];
    const float* W2    = (const float*)d_in[5];
    const float* b2    = (const float*)d_in[6];
    const float* W3    = (const float*)d_in[7];
    const float* b3    = (const float*)d_in[8];
    float* out = (float*)d_out;

    int N = in_sizes[0] / 11;
    int E = in_sizes[1] / 2;
    if (N > MAXN) N = MAXN;
    if (E > MAXE) E = MAXE;
    int E8 = E * 8;

    prep_edges_kernel<<<(E + 255) / 256, 256>>>(ei, E);

    if (out_size >= N * 96 + 64) {
        graph_sizes_kernel<<<1, 64>>>(batch, N, out + (size_t)N * 96);
    }

    init_kernel<<<(N + 127) / 128, 128>>>(x0, W1, N);

    // Layer 1
    scatter_kernel<<<(E8 + 255) / 256, 256>>>(E8);
    node_kernel<true><<<(N + 127) / 128, 128>>>(b1, W2, out, N, 0);

    // Layer 2
    scatter_kernel<<<(E8 + 255) / 256, 256>>>(E8);
    node_kernel<true><<<(N + 127) / 128, 128>>>(b2, W3, out, N, 1);

    // Layer 3 (no next GEMM)
    scatter_kernel<<<(E8 + 255) / 256, 256>>>(E8);
    node_kernel<false><<<(N + 127) / 128, 128>>>(b3, nullptr, out, N, 2);
}

// round 4
// speedup vs baseline: 1.0777x; 1.0777x over previous
#include <cuda_runtime.h>

// CFGGraphEncoder: 3-layer GCN, N=100000 nodes (11 feats), E=1600000 edges.
// layer(x,W,b) = tanh( (A@x + 2x)@W + b ) = tanh( A@(xW) + 2(xW) + b )
// => per layer: z = x@W ; agg = segsum(z over edges) ; x' = tanh(agg + 2z + b)
// Output: [N,96] concat(x1,x2,x3) followed by 64 graph sizes (bincount).
// Integer inputs arrive as int32.

#define MAXN 100000
#define MAXE 1600000
#define MAXE4 ((MAXE + 3) & ~3)

// Scratch (allocation-free contract: __device__ globals).
// Row index MAXN is a dummy sink for padded edges.
__device__ __align__(16) int2  g_edge[MAXE4];
__device__ __align__(16) float g_z[(MAXN + 1) * 32];
__device__ __align__(16) float g_agg[(MAXN + 1) * 32];

// ---------------------------------------------------------------------------
// Pack edge_index [2,E] (int32) -> int2; pad to multiple of 4 with dummy sink.
// ---------------------------------------------------------------------------
__global__ void prep_edges_kernel(const int* __restrict__ ei, int E, int Epad) {
    int t = blockIdx.x * blockDim.x + threadIdx.x;
    if (t >= Epad) return;
    int2 rc;
    if (t < E) {
        rc.x = ei[t];        // row (scatter target)
        rc.y = ei[E + t];    // col (gather source)
    } else {
        rc.x = MAXN;         // dummy sink row
        rc.y = MAXN;         // dummy source (zeroed by init; never read back)
    }
    g_edge[t] = rc;
}

// ---------------------------------------------------------------------------
// graph_sizes: batch_indices is SORTED -> binary search per graph id. 64 thr.
// ---------------------------------------------------------------------------
__device__ __forceinline__ int lower_bound_i(const int* __restrict__ b,
                                             int n, int v) {
    int lo = 0, hi = n;
    while (lo < hi) {
        int mid = (lo + hi) >> 1;
        if (b[mid] < v) lo = mid + 1; else hi = mid;
    }
    return lo;
}

__global__ void graph_sizes_kernel(const int* __restrict__ batch, int N,
                                   float* __restrict__ out_sizes) {
    int g = threadIdx.x;  // 0..63
    int c = lower_bound_i(batch, N, g + 1) - lower_bound_i(batch, N, g);
    out_sizes[g] = (float)c;
}

// ---------------------------------------------------------------------------
// Fast tanh: MUFU.EX2 based. |rel err| ~1e-6; tolerance is 1e-3.
// ---------------------------------------------------------------------------
__device__ __forceinline__ float fast_tanh(float x) {
    float ax = fabsf(x);
    float e  = __expf(-2.0f * ax);           // underflows to 0 for large ax
    float r  = __fdividef(1.0f - e, 1.0f + e);
    return copysignf(r, x);
}

// ---------------------------------------------------------------------------
// init: z = x0 @ W1 (x0 is [N,11]); zero agg. Thread N zeroes the dummy row.
// ---------------------------------------------------------------------------
__global__ void init_kernel(const float* __restrict__ x0,
                            const float* __restrict__ W1, int N) {
    __shared__ float sW[11 * 32];
    for (int i = threadIdx.x; i < 11 * 32; i += blockDim.x) sW[i] = W1[i];
    __syncthreads();
    int i = blockIdx.x * blockDim.x + threadIdx.x;
    if (i > N) return;

    float4* zp = (float4*)(g_z + (size_t)i * 32);
    float4* ap = (float4*)(g_agg + (size_t)i * 32);

    if (i == N) {   // dummy sink row: keep finite so red-add stays clean
#pragma unroll
        for (int q = 0; q < 8; q++) {
            zp[q] = make_float4(0.f, 0.f, 0.f, 0.f);
            ap[q] = make_float4(0.f, 0.f, 0.f, 0.f);
        }
        return;
    }

    float x[11];
#pragma unroll
    for (int k = 0; k < 11; k++) x[k] = x0[i * 11 + k];

#pragma unroll
    for (int q = 0; q < 8; q++) {
        float4 acc = make_float4(0.f, 0.f, 0.f, 0.f);
#pragma unroll
        for (int k = 0; k < 11; k++) {
            float xv = x[k];
            const float* w = &sW[k * 32 + q * 4];
            acc.x += xv * w[0];
            acc.y += xv * w[1];
            acc.z += xv * w[2];
            acc.w += xv * w[3];
        }
        zp[q] = acc;
        ap[q] = make_float4(0.f, 0.f, 0.f, 0.f);
    }
}

// ---------------------------------------------------------------------------
// scatter: agg[row] += z[col]. 4 edges per thread (MLP=4).
// t = (group<<3)|quad; group g owns edges 4g..4g+3; thread handles quad q
// (one float4 slice) of each. 4 gathers issued back-to-back, then 4
// fire-and-forget red.global.add.v4.f32 (REDG path, no return latency).
// ---------------------------------------------------------------------------
__device__ __forceinline__ void red_v4(float* a, float4 v) {
    asm volatile("red.global.add.v4.f32 [%0], {%1,%2,%3,%4};"
                 :: "l"(a), "f"(v.x), "f"(v.y), "f"(v.z), "f"(v.w)
                 : "memory");
}

__global__ void scatter_kernel(int ngroups) {
    int t = blockIdx.x * blockDim.x + threadIdx.x;
    int g = t >> 3;
    int q = t & 7;
    if (g >= ngroups) return;

    const int4* ep = (const int4*)g_edge;      // 2 edges per int4
    int4 e01 = __ldg(ep + 2 * g);              // (r0,c0, r1,c1)
    int4 e23 = __ldg(ep + 2 * g + 1);          // (r2,c2, r3,c3)

    const float4* zp = (const float4*)g_z;
    float4 v0 = __ldg(zp + (size_t)e01.y * 8 + q);
    float4 v1 = __ldg(zp + (size_t)e01.w * 8 + q);
    float4 v2 = __ldg(zp + (size_t)e23.y * 8 + q);
    float4 v3 = __ldg(zp + (size_t)e23.w * 8 + q);

    int qo = q * 4;
    red_v4(g_agg + (size_t)e01.x * 32 + qo, v0);
    red_v4(g_agg + (size_t)e01.z * 32 + qo, v1);
    red_v4(g_agg + (size_t)e23.x * 32 + qo, v2);
    red_v4(g_agg + (size_t)e23.z * 32 + qo, v3);
}

// ---------------------------------------------------------------------------
// node epilogue + next-layer GEMM fused:
//   h = tanh(agg + 2z + b)          -> out[:, 32*layer : 32*layer+32]
//   if HAS_NEXT: z = h @ Wn ; agg = 0
// ---------------------------------------------------------------------------
template <bool HAS_NEXT>
__global__ void node_kernel(const float* __restrict__ bvec,
                            const float* __restrict__ Wn,
                            float* __restrict__ out, int N, int layer) {
    __shared__ float sW[32 * 32];
    __shared__ float sb[32];
    if (threadIdx.x < 32) sb[threadIdx.x] = bvec[threadIdx.x];
    if (HAS_NEXT) {
        for (int i = threadIdx.x; i < 1024; i += blockDim.x) sW[i] = Wn[i];
    }
    __syncthreads();

    int i = blockIdx.x * blockDim.x + threadIdx.x;
    if (i >= N) return;

    float4* zp = (float4*)(g_z + (size_t)i * 32);
    float4* ap = (float4*)(g_agg + (size_t)i * 32);

    float h[32];
#pragma unroll
    for (int q = 0; q < 8; q++) {
        float4 a = ap[q];
        float4 z = zp[q];
        h[q * 4 + 0] = fast_tanh(a.x + 2.f * z.x + sb[q * 4 + 0]);
        h[q * 4 + 1] = fast_tanh(a.y + 2.f * z.y + sb[q * 4 + 1]);
        h[q * 4 + 2] = fast_tanh(a.z + 2.f * z.z + sb[q * 4 + 2]);
        h[q * 4 + 3] = fast_tanh(a.w + 2.f * z.w + sb[q * 4 + 3]);
    }

    float4* op = (float4*)(out + (size_t)i * 96 + 32 * layer);
#pragma unroll
    for (int q = 0; q < 8; q++) {
        op[q] = make_float4(h[q * 4 + 0], h[q * 4 + 1], h[q * 4 + 2], h[q * 4 + 3]);
    }

    if (HAS_NEXT) {
#pragma unroll
        for (int q = 0; q < 8; q++) {
            float4 acc = make_float4(0.f, 0.f, 0.f, 0.f);
#pragma unroll
            for (int k = 0; k < 32; k++) {
                float hv = h[k];
                const float* w = &sW[k * 32 + q * 4];
                acc.x += hv * w[0];
                acc.y += hv * w[1];
                acc.z += hv * w[2];
                acc.w += hv * w[3];
            }
            zp[q] = acc;
            ap[q] = make_float4(0.f, 0.f, 0.f, 0.f);
        }
    }
}

// ---------------------------------------------------------------------------
// Launch
// ---------------------------------------------------------------------------
extern "C" void kernel_launch(void* const* d_in, const int* in_sizes, int n_in,
                              void* d_out, int out_size) {
    const float* x0    = (const float*)d_in[0];
    const int*   ei    = (const int*)d_in[1];
    const int*   batch = (const int*)d_in[2];
    const float* W1    = (const float*)d_in[3];
    const float* b1    = (const float*)d_in[4];
    const float* W2    = (const float*)d_in[5];
    const float* b2    = (const float*)d_in[6];
    const float* W3    = (const float*)d_in[7];
    const float* b3    = (const float*)d_in[8];
    float* out = (float*)d_out;

    int N = in_sizes[0] / 11;
    int E = in_sizes[1] / 2;
    if (N > MAXN) N = MAXN;
    if (E > MAXE) E = MAXE;
    int Epad    = (E + 3) & ~3;
    int ngroups = Epad / 4;
    int nthr    = ngroups * 8;

    prep_edges_kernel<<<(Epad + 255) / 256, 256>>>(ei, E, Epad);

    if (out_size >= N * 96 + 64) {
        graph_sizes_kernel<<<1, 64>>>(batch, N, out + (size_t)N * 96);
    }

    init_kernel<<<(N + 1 + 127) / 128, 128>>>(x0, W1, N);

    // Layer 1
    scatter_kernel<<<(nthr + 255) / 256, 256>>>(ngroups);
    node_kernel<true><<<(N + 127) / 128, 128>>>(b1, W2, out, N, 0);

    // Layer 2
    scatter_kernel<<<(nthr + 255) / 256, 256>>>(ngroups);
    node_kernel<true><<<(N + 127) / 128, 128>>>(b2, W3, out, N, 1);

    // Layer 3 (no next GEMM)
    scatter_kernel<<<(nthr + 255) / 256, 256>>>(ngroups);
    node_kernel<false><<<(N + 127) / 128, 128>>>(b3, nullptr, out, N, 2);
}

// round 6
// speedup vs baseline: 1.4416x; 1.3377x over previous
#include <cuda_runtime.h>

// CFGGraphEncoder: 3-layer GCN, N=100000 nodes (11 feats), E=1600000 edges.
// layer(x,W,b) = tanh( (A@x + 2x)@W + b ) = tanh( A@(xW) + 2(xW) + b )
// => per layer: z = x@W ; agg = gather-sum(z over CSR) ; x' = tanh(agg+2z+b)
// CSR rebuilt every launch; aggregation is a GATHER (no hot-path atomics).
// Output: [N,96] concat(x1,x2,x3) then 64 graph sizes. Int inputs are int32.
// NOTE: __device__ globals are referenced ONLY inside device code (passing
// them as host-side kernel args resolves to the host shadow symbol -> UB).

#define MAXN 100000
#define MAXE 1600000
#define SCAN_BLK 1024

// Scratch (allocation-free contract: __device__ globals)
__device__ int   g_deg[MAXN];
__device__ int   g_partial[MAXN];
__device__ int   g_bsums[SCAN_BLK];
__device__ int   g_row_start[MAXN + 1];
__device__ int   g_cursor[MAXN];
__device__ int   g_csr_col[MAXE];
__device__ __align__(16) float g_za[MAXN * 32];
__device__ __align__(16) float g_zb[MAXN * 32];

// ---------------------------------------------------------------------------
// CSR build: zero -> histogram -> 3-phase exclusive scan -> fill
// ---------------------------------------------------------------------------
__global__ void zero_deg_kernel(int N) {
    int i = blockIdx.x * blockDim.x + threadIdx.x;
    if (i < N) g_deg[i] = 0;
}

__global__ void hist_kernel(const int* __restrict__ ei, int E) {
    int t = blockIdx.x * blockDim.x + threadIdx.x;
    if (t < E) atomicAdd(&g_deg[ei[t]], 1);
}

__global__ void scan1_kernel(int N) {
    __shared__ int s[SCAN_BLK];
    int i = blockIdx.x * SCAN_BLK + threadIdx.x;
    int v = (i < N) ? g_deg[i] : 0;
    s[threadIdx.x] = v;
    __syncthreads();
#pragma unroll
    for (int off = 1; off < SCAN_BLK; off <<= 1) {
        int t = (threadIdx.x >= off) ? s[threadIdx.x - off] : 0;
        __syncthreads();
        s[threadIdx.x] += t;
        __syncthreads();
    }
    if (i < N) g_partial[i] = s[threadIdx.x] - v;           // exclusive
    if (threadIdx.x == SCAN_BLK - 1) g_bsums[blockIdx.x] = s[threadIdx.x];
}

__global__ void scan2_kernel(int nb) {                       // 1 block
    __shared__ int s[SCAN_BLK];
    int v = (threadIdx.x < nb) ? g_bsums[threadIdx.x] : 0;
    s[threadIdx.x] = v;
    __syncthreads();
#pragma unroll
    for (int off = 1; off < SCAN_BLK; off <<= 1) {
        int t = (threadIdx.x >= off) ? s[threadIdx.x - off] : 0;
        __syncthreads();
        s[threadIdx.x] += t;
        __syncthreads();
    }
    if (threadIdx.x < nb) g_bsums[threadIdx.x] = s[threadIdx.x] - v;  // excl
}

__global__ void scan3_kernel(int N, int E) {
    int i = blockIdx.x * SCAN_BLK + threadIdx.x;
    if (i < N) {
        int rs = g_partial[i] + g_bsums[blockIdx.x];
        g_row_start[i] = rs;
        g_cursor[i]    = rs;
    }
    if (i == 0) g_row_start[N] = E;
}

__global__ void fill_kernel(const int* __restrict__ ei, int E) {
    int t = blockIdx.x * blockDim.x + threadIdx.x;
    if (t < E) {
        int r = ei[t];
        int c = ei[E + t];
        int pos = atomicAdd(&g_cursor[r], 1);
        g_csr_col[pos] = c;
    }
}

// ---------------------------------------------------------------------------
// graph_sizes: batch sorted -> binary search per graph id. 64 threads.
// ---------------------------------------------------------------------------
__device__ __forceinline__ int lower_bound_i(const int* __restrict__ b,
                                             int n, int v) {
    int lo = 0, hi = n;
    while (lo < hi) {
        int mid = (lo + hi) >> 1;
        if (b[mid] < v) lo = mid + 1; else hi = mid;
    }
    return lo;
}

__global__ void graph_sizes_kernel(const int* __restrict__ batch, int N,
                                   float* __restrict__ out_sizes) {
    int g = threadIdx.x;
    int c = lower_bound_i(batch, N, g + 1) - lower_bound_i(batch, N, g);
    out_sizes[g] = (float)c;
}

// ---------------------------------------------------------------------------
// Fast tanh (MUFU path). |rel err| ~1e-6; tolerance 1e-3.
// ---------------------------------------------------------------------------
__device__ __forceinline__ float fast_tanh(float x) {
    float ax = fabsf(x);
    float e  = __expf(-2.0f * ax);
    float r  = __fdividef(1.0f - e, 1.0f + e);
    return copysignf(r, x);
}

// ---------------------------------------------------------------------------
// init: za = x0 @ W1 (x0 is [N,11]). One thread per node.
// ---------------------------------------------------------------------------
__global__ void init_kernel(const float* __restrict__ x0,
                            const float* __restrict__ W1, int N) {
    __shared__ float sW[11 * 32];
    for (int i = threadIdx.x; i < 11 * 32; i += blockDim.x) sW[i] = W1[i];
    __syncthreads();
    int i = blockIdx.x * blockDim.x + threadIdx.x;
    if (i >= N) return;

    float x[11];
#pragma unroll
    for (int k = 0; k < 11; k++) x[k] = x0[i * 11 + k];

    float4* zp = (float4*)(g_za + (size_t)i * 32);
#pragma unroll
    for (int q = 0; q < 8; q++) {
        float4 acc = make_float4(0.f, 0.f, 0.f, 0.f);
#pragma unroll
        for (int k = 0; k < 11; k++) {
            float xv = x[k];
            const float* w = &sW[k * 32 + q * 4];
            acc.x += xv * w[0];
            acc.y += xv * w[1];
            acc.z += xv * w[2];
            acc.w += xv * w[3];
        }
        zp[q] = acc;
    }
}

// ---------------------------------------------------------------------------
// Fused layer: gather + epilogue + (optional) next-layer GEMM.
// 8 threads per node (quad q), 32 nodes per 256-thread block.
// PING=true: zin=g_za, zout=g_zb;  PING=false: zin=g_zb, zout=g_za.
// Gather: per neighbor, the 8 group threads read one 128B z row coalesced;
// 2-way unrolled for MLP. h = tanh(agg + 2z + b) -> out slice; if HAS_NEXT,
// z' = h @ Wn via padded smem exchange (stride 33, conflict-free).
// ---------------------------------------------------------------------------
template <bool HAS_NEXT, bool PING>
__global__ void layer_kernel(const float* __restrict__ bvec,
                             const float* __restrict__ Wn,
                             float* __restrict__ out, int N, int layer) {
    const float* zin  = PING ? g_za : g_zb;
    float*       zout = PING ? g_zb : g_za;

    __shared__ float sW[32 * 32];
    __shared__ float sb[32];
    __shared__ float sh[32 * 33];       // 32 nodes x 32 h, stride 33

    int tid = threadIdx.x;
    if (tid < 32) sb[tid] = bvec[tid];
    if (HAS_NEXT) {
        for (int i = tid; i < 1024; i += 256) sW[i] = Wn[i];
    }
    __syncthreads();

    int nl   = tid >> 3;                // node-local 0..31
    int q    = tid & 7;                 // quad 0..7
    int node = blockIdx.x * 32 + nl;
    bool act = node < N;

    float4 acc0 = make_float4(0.f, 0.f, 0.f, 0.f);
    float4 acc1 = make_float4(0.f, 0.f, 0.f, 0.f);
    float4 zq   = make_float4(0.f, 0.f, 0.f, 0.f);

    if (act) {
        int s = g_row_start[node];
        int e = g_row_start[node + 1];
        const float4* zp = (const float4*)zin;
        int j = s;
        for (; j + 1 < e; j += 2) {
            int c0 = __ldg(&g_csr_col[j]);
            int c1 = __ldg(&g_csr_col[j + 1]);
            float4 v0 = __ldg(zp + (size_t)c0 * 8 + q);
            float4 v1 = __ldg(zp + (size_t)c1 * 8 + q);
            acc0.x += v0.x; acc0.y += v0.y; acc0.z += v0.z; acc0.w += v0.w;
            acc1.x += v1.x; acc1.y += v1.y; acc1.z += v1.z; acc1.w += v1.w;
        }
        if (j < e) {
            int c = __ldg(&g_csr_col[j]);
            float4 v = __ldg(zp + (size_t)c * 8 + q);
            acc0.x += v.x; acc0.y += v.y; acc0.z += v.z; acc0.w += v.w;
        }
        zq = __ldg((const float4*)zin + (size_t)node * 8 + q);
    }

    float4 h;
    h.x = fast_tanh(acc0.x + acc1.x + 2.f * zq.x + sb[q * 4 + 0]);
    h.y = fast_tanh(acc0.y + acc1.y + 2.f * zq.y + sb[q * 4 + 1]);
    h.z = fast_tanh(acc0.z + acc1.z + 2.f * zq.z + sb[q * 4 + 2]);
    h.w = fast_tanh(acc0.w + acc1.w + 2.f * zq.w + sb[q * 4 + 3]);

    if (act) {
        ((float4*)(out + (size_t)node * 96 + 32 * layer))[q] = h;
    }

    if (HAS_NEXT) {
        int hb = nl * 33 + q * 4;
        sh[hb + 0] = h.x; sh[hb + 1] = h.y; sh[hb + 2] = h.z; sh[hb + 3] = h.w;
        __syncthreads();

        float4 zacc = make_float4(0.f, 0.f, 0.f, 0.f);
#pragma unroll
        for (int k = 0; k < 32; k++) {
            float hv = sh[nl * 33 + k];
            const float* w = &sW[k * 32 + q * 4];
            zacc.x += hv * w[0];
            zacc.y += hv * w[1];
            zacc.z += hv * w[2];
            zacc.w += hv * w[3];
        }
        if (act) {
            ((float4*)zout)[(size_t)node * 8 + q] = zacc;
        }
    }
}

// ---------------------------------------------------------------------------
// Launch
// ---------------------------------------------------------------------------
extern "C" void kernel_launch(void* const* d_in, const int* in_sizes, int n_in,
                              void* d_out, int out_size) {
    const float* x0    = (const float*)d_in[0];
    const int*   ei    = (const int*)d_in[1];
    const int*   batch = (const int*)d_in[2];
    const float* W1    = (const float*)d_in[3];
    const float* b1    = (const float*)d_in[4];
    const float* W2    = (const float*)d_in[5];
    const float* b2    = (const float*)d_in[6];
    const float* W3    = (const float*)d_in[7];
    const float* b3    = (const float*)d_in[8];
    float* out = (float*)d_out;

    int N = in_sizes[0] / 11;
    int E = in_sizes[1] / 2;
    if (N > MAXN) N = MAXN;
    if (E > MAXE) E = MAXE;
    int nb = (N + SCAN_BLK - 1) / SCAN_BLK;   // <= 98 <= 1024

    // CSR build
    zero_deg_kernel<<<(N + 255) / 256, 256>>>(N);
    hist_kernel<<<(E + 255) / 256, 256>>>(ei, E);
    scan1_kernel<<<nb, SCAN_BLK>>>(N);
    scan2_kernel<<<1, SCAN_BLK>>>(nb);
    scan3_kernel<<<nb, SCAN_BLK>>>(N, E);
    fill_kernel<<<(E + 255) / 256, 256>>>(ei, E);

    if (out_size >= N * 96 + 64) {
        graph_sizes_kernel<<<1, 64>>>(batch, N, out + (size_t)N * 96);
    }

    init_kernel<<<(N + 127) / 128, 128>>>(x0, W1, N);

    int lgrid = (N + 31) / 32;
    layer_kernel<true,  true ><<<lgrid, 256>>>(b1, W2, out, N, 0);
    layer_kernel<true,  false><<<lgrid, 256>>>(b2, W3, out, N, 1);
    layer_kernel<false, true ><<<lgrid, 256>>>(b3, nullptr, out, N, 2);
}